// round 2
// baseline (speedup 1.0000x reference)
#include <cuda_runtime.h>
#include <cuda_bf16.h>

#define N_NODES   4000000
#define N_GRAPHS  4096
#define D_FEAT    8
#define N_CLASSES 10

// Scratch: segment start offsets (sorted ids -> boundaries via binary search).
__device__ int g_seg_start[N_GRAPHS + 1];

// Kernel 1: one thread per segment id computes lower_bound(batch_ids, g).
// batch_ids may be int64 OR int32 (JAX silently downcasts int64 under default
// x64=False). Detect: viewing the buffer as int32, index N_NODES-1 is the
// high word of an int64 element (== 0) in the 64-bit case, or the max sorted
// id (> 0) in the 32-bit case.
__global__ void seg_bounds_kernel(const int* __restrict__ ids32,
                                  int* __restrict__ seg_start) {
    int g = blockIdx.x * blockDim.x + threadIdx.x;
    if (g > N_GRAPHS) return;
    if (g == N_GRAPHS) { seg_start[g] = N_NODES; return; }

    const bool is64 = (ids32[N_NODES - 1] == 0);

    int lo = 0, hi = N_NODES;
    if (is64) {
        const long long* ids = (const long long*)ids32;
        const long long gg = (long long)g;
        while (lo < hi) {
            int mid = (lo + hi) >> 1;
            if (ids[mid] < gg) lo = mid + 1; else hi = mid;
        }
    } else {
        while (lo < hi) {
            int mid = (lo + hi) >> 1;
            if (ids32[mid] < g) lo = mid + 1; else hi = mid;
        }
    }
    seg_start[g] = lo;
}

// Kernel 2: one warp per segment. Flat float4 streaming read of the segment's
// rows (8 floats/row = 2 float4/row -> lane parity fixes which 4 columns a
// lane accumulates). Parity-preserving butterfly reduce, then fused GEMM.
__global__ __launch_bounds__(256) void pool_gemm_kernel(
    const float4* __restrict__ x4,
    const int* __restrict__ seg_start,
    const float* __restrict__ W,   // [10, 8] row-major
    const float* __restrict__ b,   // [10]
    float* __restrict__ out)       // [4096, 10]
{
    const int warp = threadIdx.x >> 5;
    const int lane = threadIdx.x & 31;
    const int g = blockIdx.x * (blockDim.x >> 5) + warp;   // segment id
    if (g >= N_GRAPHS) return;

    const int start = seg_start[g];
    const int end   = seg_start[g + 1];
    const int cnt   = end - start;
    const long long base = (long long)start * 2;   // float4 units
    const int n4 = cnt * 2;                        // float4 count

    float4 a0 = make_float4(0.f, 0.f, 0.f, 0.f);
    float4 a1 = make_float4(0.f, 0.f, 0.f, 0.f);

    int j = lane;
    while (j + 32 < n4) {
        float4 v0 = __ldg(&x4[base + j]);
        float4 v1 = __ldg(&x4[base + j + 32]);
        a0.x += v0.x; a0.y += v0.y; a0.z += v0.z; a0.w += v0.w;
        a1.x += v1.x; a1.y += v1.y; a1.z += v1.z; a1.w += v1.w;
        j += 64;
    }
    if (j < n4) {
        float4 v0 = __ldg(&x4[base + j]);
        a0.x += v0.x; a0.y += v0.y; a0.z += v0.z; a0.w += v0.w;
    }
    a0.x += a1.x; a0.y += a1.y; a0.z += a1.z; a0.w += a1.w;

    // Butterfly over masks 16,8,4,2: preserves lane parity, so after this
    // every even lane holds full sums for cols 0-3, every odd lane cols 4-7.
    #pragma unroll
    for (int m = 16; m >= 2; m >>= 1) {
        a0.x += __shfl_xor_sync(0xFFFFFFFFu, a0.x, m);
        a0.y += __shfl_xor_sync(0xFFFFFFFFu, a0.y, m);
        a0.z += __shfl_xor_sync(0xFFFFFFFFu, a0.z, m);
        a0.w += __shfl_xor_sync(0xFFFFFFFFu, a0.w, m);
    }

    __shared__ float pooled[8][8];   // [warp][col]
    const float inv = (cnt > 0) ? (1.0f / (float)cnt) : 0.0f;
    if (lane == 0) {
        pooled[warp][0] = a0.x * inv; pooled[warp][1] = a0.y * inv;
        pooled[warp][2] = a0.z * inv; pooled[warp][3] = a0.w * inv;
    } else if (lane == 1) {
        pooled[warp][4] = a0.x * inv; pooled[warp][5] = a0.y * inv;
        pooled[warp][6] = a0.z * inv; pooled[warp][7] = a0.w * inv;
    }
    __syncwarp(0xFFFFFFFFu);

    if (lane < N_CLASSES) {
        float acc = b[lane];
        #pragma unroll
        for (int k = 0; k < D_FEAT; k++)
            acc += pooled[warp][k] * W[lane * D_FEAT + k];
        out[(long long)g * N_CLASSES + lane] = acc;
    }
}

extern "C" void kernel_launch(void* const* d_in, const int* in_sizes, int n_in,
                              void* d_out, int out_size) {
    // Bind inputs by element count (robust to metadata ordering):
    //   x: 32,000,000 f32 | batch_ids: 4,000,000 | W: 80 | b: 10
    const float* x   = nullptr;
    const void*  ids = nullptr;
    const float* W   = nullptr;
    const float* b   = nullptr;
    for (int i = 0; i < n_in; i++) {
        switch (in_sizes[i]) {
            case N_NODES * D_FEAT:       x   = (const float*)d_in[i]; break;
            case N_NODES:                ids = d_in[i];               break;
            case N_CLASSES * D_FEAT:     W   = (const float*)d_in[i]; break;
            case N_CLASSES:              b   = (const float*)d_in[i]; break;
            default: break; // input_ids / attention_mask: unused
        }
    }
    float* out = (float*)d_out;

    int* seg_start = nullptr;
    cudaGetSymbolAddress((void**)&seg_start, g_seg_start);

    seg_bounds_kernel<<<(N_GRAPHS + 1 + 255) / 256, 256>>>(
        (const int*)ids, seg_start);

    // 4096 segments, 8 warps (256 threads) per block -> 512 blocks
    pool_gemm_kernel<<<N_GRAPHS / 8, 256>>>(
        (const float4*)x, seg_start, W, b, out);
}

// round 3
// speedup vs baseline: 1.1215x; 1.1215x over previous
#include <cuda_runtime.h>
#include <cuda_bf16.h>

#define N_NODES   4000000
#define N_GRAPHS  4096
#define D_FEAT    8
#define N_CLASSES 10
#define WARPS_PER_BLOCK 8
#define N_BLOCKS (N_GRAPHS / WARPS_PER_BLOCK)

// lower_bound over sorted batch_ids for value g. Handles int64 or int32 ids
// (JAX under default x64=False silently downcasts int64 -> int32; detect by
// viewing as int32: element N_NODES-1 is the high word of an int64 (==0) in
// the 64-bit case, or the max sorted id (>0) in the 32-bit case).
__device__ __forceinline__ int lower_bound_ids(const int* __restrict__ ids32,
                                               bool is64, int g, int lo, int hi) {
    if (is64) {
        const long long* ids = (const long long*)ids32;
        const long long gg = (long long)g;
        while (lo < hi) {
            int mid = (lo + hi) >> 1;
            if (ids[mid] < gg) lo = mid + 1; else hi = mid;
        }
    } else {
        while (lo < hi) {
            int mid = (lo + hi) >> 1;
            if (ids32[mid] < g) lo = mid + 1; else hi = mid;
        }
    }
    return lo;
}

__device__ __forceinline__ int id_at(const int* __restrict__ ids32, bool is64, int i) {
    return is64 ? (int)((const long long*)ids32)[i] : ids32[i];
}

// Fused kernel: per-block boundary search (9 threads) + warp-per-segment
// float4 streaming reduction (unroll 8) + parity butterfly + tiny GEMM.
__global__ __launch_bounds__(256) void fused_pool_gemm_kernel(
    const float4* __restrict__ x4,
    const int*    __restrict__ ids32,  // batch_ids (int32 or int64 raw)
    const float*  __restrict__ W,      // [10, 8] row-major
    const float*  __restrict__ b,      // [10]
    float*        __restrict__ out)    // [4096, 10]
{
    __shared__ int   bounds[WARPS_PER_BLOCK + 1];
    __shared__ float pooled[WARPS_PER_BLOCK][D_FEAT];

    const int tid  = threadIdx.x;
    const int warp = tid >> 5;
    const int lane = tid & 31;
    const int g0   = blockIdx.x * WARPS_PER_BLOCK;

    // ---- Phase 1: boundary search (threads 0..8) ----
    if (tid <= WARPS_PER_BLOCK) {
        const int g = g0 + tid;
        if (g >= N_GRAPHS) {
            bounds[tid] = N_NODES;
        } else {
            const bool is64 = (ids32[N_NODES - 1] == 0);
            // Windowed search around expected position (uniform ids):
            // start of segment g ~ Binomial(N, g/B), sd <= ~1000. +-32768 = 32 sd.
            long long approx = ((long long)g * N_NODES) >> 12;   // g * N/B
            int lo = (int)(approx - 32768); if (lo < 0) lo = 0;
            int hi = (int)(approx + 32768); if (hi > N_NODES) hi = N_NODES;
            // Verify bracket: ids[lo-1] < g (or lo==0) and ids[hi-1] >= g (or hi==N).
            bool ok_lo = (lo == 0) || (id_at(ids32, is64, lo - 1) < g);
            bool ok_hi = (hi == N_NODES) || (id_at(ids32, is64, hi - 1) >= g)
                         || (id_at(ids32, is64, hi) >= g);
            if (!(ok_lo && ok_hi)) { lo = 0; hi = N_NODES; }   // fallback: full range
            bounds[tid] = lower_bound_ids(ids32, is64, g, lo, hi);
        }
    }
    __syncthreads();

    // ---- Phase 2: streaming segment reduction, one warp per segment ----
    const int g     = g0 + warp;
    const int start = bounds[warp];
    const int end   = bounds[warp + 1];
    const int cnt   = end - start;
    const long long base = (long long)start * 2;  // float4 units
    const int n4 = cnt * 2;

    float4 acc0 = make_float4(0.f,0.f,0.f,0.f);
    float4 acc1 = make_float4(0.f,0.f,0.f,0.f);
    float4 acc2 = make_float4(0.f,0.f,0.f,0.f);
    float4 acc3 = make_float4(0.f,0.f,0.f,0.f);

    int c = 0;
    while (c + 256 <= n4) {   // 8 loads x 32 lanes per chunk
        const long long p = base + c + lane;
        float4 v0 = __ldg(&x4[p      ]);
        float4 v1 = __ldg(&x4[p +  32]);
        float4 v2 = __ldg(&x4[p +  64]);
        float4 v3 = __ldg(&x4[p +  96]);
        float4 v4 = __ldg(&x4[p + 128]);
        float4 v5 = __ldg(&x4[p + 160]);
        float4 v6 = __ldg(&x4[p + 192]);
        float4 v7 = __ldg(&x4[p + 224]);
        acc0.x += v0.x; acc0.y += v0.y; acc0.z += v0.z; acc0.w += v0.w;
        acc1.x += v1.x; acc1.y += v1.y; acc1.z += v1.z; acc1.w += v1.w;
        acc2.x += v2.x; acc2.y += v2.y; acc2.z += v2.z; acc2.w += v2.w;
        acc3.x += v3.x; acc3.y += v3.y; acc3.z += v3.z; acc3.w += v3.w;
        acc0.x += v4.x; acc0.y += v4.y; acc0.z += v4.z; acc0.w += v4.w;
        acc1.x += v5.x; acc1.y += v5.y; acc1.z += v5.z; acc1.w += v5.w;
        acc2.x += v6.x; acc2.y += v6.y; acc2.z += v6.z; acc2.w += v6.w;
        acc3.x += v7.x; acc3.y += v7.y; acc3.z += v7.z; acc3.w += v7.w;
        c += 256;
    }
    for (int j = c + lane; j < n4; j += 32) {   // tail
        float4 v = __ldg(&x4[base + j]);
        acc0.x += v.x; acc0.y += v.y; acc0.z += v.z; acc0.w += v.w;
    }
    acc0.x += acc1.x + acc2.x + acc3.x;
    acc0.y += acc1.y + acc2.y + acc3.y;
    acc0.z += acc1.z + acc2.z + acc3.z;
    acc0.w += acc1.w + acc2.w + acc3.w;

    // Parity-preserving butterfly (masks 16,8,4,2): even lanes end with full
    // sums of cols 0-3, odd lanes cols 4-7.
    #pragma unroll
    for (int m = 16; m >= 2; m >>= 1) {
        acc0.x += __shfl_xor_sync(0xFFFFFFFFu, acc0.x, m);
        acc0.y += __shfl_xor_sync(0xFFFFFFFFu, acc0.y, m);
        acc0.z += __shfl_xor_sync(0xFFFFFFFFu, acc0.z, m);
        acc0.w += __shfl_xor_sync(0xFFFFFFFFu, acc0.w, m);
    }

    const float inv = (cnt > 0) ? (1.0f / (float)cnt) : 0.0f;
    if (lane == 0) {
        pooled[warp][0] = acc0.x * inv; pooled[warp][1] = acc0.y * inv;
        pooled[warp][2] = acc0.z * inv; pooled[warp][3] = acc0.w * inv;
    } else if (lane == 1) {
        pooled[warp][4] = acc0.x * inv; pooled[warp][5] = acc0.y * inv;
        pooled[warp][6] = acc0.z * inv; pooled[warp][7] = acc0.w * inv;
    }
    __syncwarp(0xFFFFFFFFu);

    // ---- Phase 3: fused tiny GEMM: out[g,:] = pooled @ W^T + b ----
    if (lane < N_CLASSES) {
        float r = b[lane];
        #pragma unroll
        for (int k = 0; k < D_FEAT; k++)
            r += pooled[warp][k] * W[lane * D_FEAT + k];
        out[(long long)g * N_CLASSES + lane] = r;
    }
}

extern "C" void kernel_launch(void* const* d_in, const int* in_sizes, int n_in,
                              void* d_out, int out_size) {
    // Bind inputs by element count (robust to metadata ordering):
    //   x: 32,000,000 f32 | batch_ids: 4,000,000 | W: 80 | b: 10
    const float* x   = nullptr;
    const void*  ids = nullptr;
    const float* W   = nullptr;
    const float* b   = nullptr;
    for (int i = 0; i < n_in; i++) {
        switch (in_sizes[i]) {
            case N_NODES * D_FEAT:   x   = (const float*)d_in[i]; break;
            case N_NODES:            ids = d_in[i];               break;
            case N_CLASSES * D_FEAT: W   = (const float*)d_in[i]; break;
            case N_CLASSES:          b   = (const float*)d_in[i]; break;
            default: break; // input_ids / attention_mask: unused
        }
    }
    float* out = (float*)d_out;

    fused_pool_gemm_kernel<<<N_BLOCKS, 256>>>(
        (const float4*)x, (const int*)ids, W, b, out);
}

// round 4
// speedup vs baseline: 1.2859x; 1.1466x over previous
#include <cuda_runtime.h>
#include <cuda_bf16.h>

#define N_NODES   4000000
#define N_GRAPHS  4096
#define D_FEAT    8
#define N_CLASSES 10
#define WARPS_PER_BLOCK 4
#define N_BLOCKS (N_GRAPHS / WARPS_PER_BLOCK)
#define FULL 0xFFFFFFFFu

// batch_ids may be int64 OR int32 (JAX under default x64=False silently makes
// them int32). Values < 4096 so in the int64 case every high word is 0:
// detect via ids32[2*N-1... ] -- we view as int32 and check the last element:
// int64 -> high word == 0 ; int32 -> max id > 0.
__device__ __forceinline__ int id_at(const int* __restrict__ ids32, bool is64, int i) {
    return is64 ? ids32[2 * i] : ids32[i];   // little-endian low word holds the value
}

// Half-warp cooperative 16-ary lower_bound of v over sorted ids in [lo, hi].
// All 16 lanes of one half execute together (hmask ballots). Returns first
// index with ids[idx] >= v. ~log16 dependent probe rounds.
__device__ __forceinline__ int kary_lower_bound(
    const int* __restrict__ ids32, bool is64, int v,
    int lo, int hi, int sub, int half_shift)
{
    const unsigned hmask = 0xFFFFu << half_shift;
    while (hi - lo > 16) {
        const int range = hi - lo;
        const int pos = lo + (int)(((long long)range * (sub + 1)) >> 4); // in [lo+1, hi]
        const bool less = id_at(ids32, is64, pos - 1) < v;
        const unsigned ball = __ballot_sync(hmask, less);
        const int cnt = __popc((ball >> half_shift) & 0xFFFFu);  // monotone prefix
        const int nlo = lo + (int)(((long long)range * cnt) >> 4);
        const int nhi = (cnt == 16) ? hi
                      : lo + (int)(((long long)range * (cnt + 1)) >> 4);
        lo = nlo; hi = nhi;
    }
    // final: <=16 candidates, one probe per lane
    const int pos = lo + sub;
    const bool less = (pos < hi) ? (id_at(ids32, is64, pos) < v) : false;
    const unsigned ball = __ballot_sync(hmask, less);
    return lo + __popc((ball >> half_shift) & 0xFFFFu);
}

__global__ __launch_bounds__(128) void fused_pool_gemm_kernel(
    const float4* __restrict__ x4,
    const int*    __restrict__ ids32,
    const float*  __restrict__ W,      // [10, 8]
    const float*  __restrict__ b,      // [10]
    float*        __restrict__ out)    // [4096, 10]
{
    const int warp = threadIdx.x >> 5;
    const int lane = threadIdx.x & 31;
    const int g    = blockIdx.x * WARPS_PER_BLOCK + warp;   // segment id

    // ---- Phase 1: per-warp cooperative boundary search (no block sync) ----
    const bool is64 = (ids32[N_NODES - 1] == 0);   // see comment at id_at
    const int half_shift = lane & 16;
    const int sub = lane & 15;
    const int v = (half_shift == 0) ? g : g + 1;   // lower half: start; upper: end

    int res;
    if (v >= N_GRAPHS) {
        res = N_NODES;
    } else {
        // Windowed: expected start of segment v ~ v*N/B, sd ~1000; +-32768 = 32 sd.
        const long long approx = ((long long)v * N_NODES) >> 12;
        int lo = (int)(approx - 32768); if (lo < 0) lo = 0;
        int hi = (int)(approx + 32768); if (hi > N_NODES) hi = N_NODES;
        const bool ok_lo = (lo == 0)       || (id_at(ids32, is64, lo - 1) < v);
        const bool ok_hi = (hi == N_NODES) || (id_at(ids32, is64, hi) >= v);
        if (!(ok_lo && ok_hi)) { lo = 0; hi = N_NODES; }   // safe fallback
        res = kary_lower_bound(ids32, is64, v, lo, hi, sub, half_shift);
    }
    __syncwarp(FULL);
    const int start = __shfl_sync(FULL, res, 0);
    const int end   = __shfl_sync(FULL, res, 16);
    const int cnt   = end - start;
    const long long base = (long long)start * 2;   // float4 units
    const int n4 = cnt * 2;

    // ---- Phase 2: float4 streaming reduction, unroll 8 ----
    float4 acc0 = make_float4(0.f,0.f,0.f,0.f);
    float4 acc1 = make_float4(0.f,0.f,0.f,0.f);
    float4 acc2 = make_float4(0.f,0.f,0.f,0.f);
    float4 acc3 = make_float4(0.f,0.f,0.f,0.f);

    int c = 0;
    while (c + 256 <= n4) {
        const long long p = base + c + lane;
        float4 v0 = __ldg(&x4[p      ]);
        float4 v1 = __ldg(&x4[p +  32]);
        float4 v2 = __ldg(&x4[p +  64]);
        float4 v3 = __ldg(&x4[p +  96]);
        float4 v4 = __ldg(&x4[p + 128]);
        float4 v5 = __ldg(&x4[p + 160]);
        float4 v6 = __ldg(&x4[p + 192]);
        float4 v7 = __ldg(&x4[p + 224]);
        acc0.x += v0.x; acc0.y += v0.y; acc0.z += v0.z; acc0.w += v0.w;
        acc1.x += v1.x; acc1.y += v1.y; acc1.z += v1.z; acc1.w += v1.w;
        acc2.x += v2.x; acc2.y += v2.y; acc2.z += v2.z; acc2.w += v2.w;
        acc3.x += v3.x; acc3.y += v3.y; acc3.z += v3.z; acc3.w += v3.w;
        acc0.x += v4.x; acc0.y += v4.y; acc0.z += v4.z; acc0.w += v4.w;
        acc1.x += v5.x; acc1.y += v5.y; acc1.z += v5.z; acc1.w += v5.w;
        acc2.x += v6.x; acc2.y += v6.y; acc2.z += v6.z; acc2.w += v6.w;
        acc3.x += v7.x; acc3.y += v7.y; acc3.z += v7.z; acc3.w += v7.w;
        c += 256;
    }
    for (int j = c + lane; j < n4; j += 32) {
        float4 vv = __ldg(&x4[base + j]);
        acc0.x += vv.x; acc0.y += vv.y; acc0.z += vv.z; acc0.w += vv.w;
    }
    acc0.x += acc1.x + acc2.x + acc3.x;
    acc0.y += acc1.y + acc2.y + acc3.y;
    acc0.z += acc1.z + acc2.z + acc3.z;
    acc0.w += acc1.w + acc2.w + acc3.w;

    // Parity-preserving butterfly: lane 0 ends with cols 0-3, lane 1 cols 4-7.
    #pragma unroll
    for (int m = 16; m >= 2; m >>= 1) {
        acc0.x += __shfl_xor_sync(FULL, acc0.x, m);
        acc0.y += __shfl_xor_sync(FULL, acc0.y, m);
        acc0.z += __shfl_xor_sync(FULL, acc0.z, m);
        acc0.w += __shfl_xor_sync(FULL, acc0.w, m);
    }

    // ---- Phase 3: broadcast pooled vector via shuffles, fused tiny GEMM ----
    const float inv = (cnt > 0) ? (1.0f / (float)cnt) : 0.0f;
    const float p0 = __shfl_sync(FULL, acc0.x, 0) * inv;
    const float p1 = __shfl_sync(FULL, acc0.y, 0) * inv;
    const float p2 = __shfl_sync(FULL, acc0.z, 0) * inv;
    const float p3 = __shfl_sync(FULL, acc0.w, 0) * inv;
    const float p4 = __shfl_sync(FULL, acc0.x, 1) * inv;
    const float p5 = __shfl_sync(FULL, acc0.y, 1) * inv;
    const float p6 = __shfl_sync(FULL, acc0.z, 1) * inv;
    const float p7 = __shfl_sync(FULL, acc0.w, 1) * inv;

    if (lane < N_CLASSES) {
        const float* w = W + lane * D_FEAT;
        float r = __ldg(&b[lane]);
        r += p0 * __ldg(&w[0]) + p1 * __ldg(&w[1]) + p2 * __ldg(&w[2]) + p3 * __ldg(&w[3]);
        r += p4 * __ldg(&w[4]) + p5 * __ldg(&w[5]) + p6 * __ldg(&w[6]) + p7 * __ldg(&w[7]);
        out[g * N_CLASSES + lane] = r;
    }
}

extern "C" void kernel_launch(void* const* d_in, const int* in_sizes, int n_in,
                              void* d_out, int out_size) {
    // Bind inputs by element count (robust to metadata ordering):
    //   x: 32,000,000 f32 | batch_ids: 4,000,000 | W: 80 | b: 10
    const float* x   = nullptr;
    const void*  ids = nullptr;
    const float* W   = nullptr;
    const float* b   = nullptr;
    for (int i = 0; i < n_in; i++) {
        switch (in_sizes[i]) {
            case N_NODES * D_FEAT:   x   = (const float*)d_in[i]; break;
            case N_NODES:            ids = d_in[i];               break;
            case N_CLASSES * D_FEAT: W   = (const float*)d_in[i]; break;
            case N_CLASSES:          b   = (const float*)d_in[i]; break;
            default: break; // input_ids / attention_mask: unused
        }
    }
    float* out = (float*)d_out;

    fused_pool_gemm_kernel<<<N_BLOCKS, 128>>>(
        (const float4*)x, (const int*)ids, W, b, out);
}